// round 10
// baseline (speedup 1.0000x reference)
#include <cuda_runtime.h>

#define FULL_MASK 0xFFFFFFFFu
typedef unsigned long long u64;

// ---------- packed f32x2 helpers (sm_100a) ----------
__device__ __forceinline__ u64 pack2(float a, float b) {
    u64 d; asm("mov.b64 %0, {%1, %2};" : "=l"(d) : "f"(a), "f"(b)); return d;
}
__device__ __forceinline__ void unpack2(u64 v, float& a, float& b) {
    asm("mov.b64 {%0, %1}, %2;" : "=f"(a), "=f"(b) : "l"(v));
}
__device__ __forceinline__ u64 fma2(u64 a, u64 b, u64 c) {
    u64 d; asm("fma.rn.f32x2 %0, %1, %2, %3;" : "=l"(d) : "l"(a), "l"(b), "l"(c)); return d;
}
__device__ __forceinline__ u64 mul2(u64 a, u64 b) {
    u64 d; asm("mul.rn.f32x2 %0, %1, %2;" : "=l"(d) : "l"(a), "l"(b)); return d;
}
__device__ __forceinline__ u64 add2(u64 a, u64 b) {
    u64 d; asm("add.rn.f32x2 %0, %1, %2;" : "=l"(d) : "l"(a), "l"(b)); return d;
}

// ---------- circuit building blocks (operate on one 8-vec state) ----------
__device__ __forceinline__ void laneRY(u64* st, int m, u64 vc2, u64 svs2) {
#pragma unroll
    for (int k = 0; k < 8; ++k) {
        float a, bb; unpack2(st[k], a, bb);
        const float pa = __shfl_xor_sync(FULL_MASK, a, m);
        const float pb = __shfl_xor_sync(FULL_MASK, bb, m);
        st[k] = fma2(vc2, st[k], mul2(svs2, pack2(pa, pb)));
    }
}
__device__ __forceinline__ void regRY(u64* st, int m2, u64 vc2, u64 vsp, u64 vsn) {
#pragma unroll
    for (int k = 0; k < 8; ++k)
        if (!(k & m2)) {
            const u64 a = st[k], bb = st[k + m2];
            st[k]      = fma2(vc2, a,  mul2(vsn, bb));
            st[k + m2] = fma2(vc2, bb, mul2(vsp, a));
        }
}
__device__ __forceinline__ void pairRY(u64* st, u64 vc2, u64 vspm) {
#pragma unroll
    for (int k = 0; k < 8; ++k) {
        float a, bb; unpack2(st[k], a, bb);
        st[k] = fma2(vc2, st[k], mul2(vspm, pack2(bb, a)));
    }
}
// Layer-1 CNOT ring tail (lane segment q0..3 deferred to logical relabeling)
__device__ __forceinline__ void ringTail(u64* st, bool hi) {
#pragma unroll
    for (int k = 0; k < 4; ++k) {
        const u64 a = st[k], bb = st[k + 4];
        st[k]     = hi ? bb : a;
        st[k + 4] = hi ? a : bb;
    }
    { u64 t = st[4]; st[4] = st[6]; st[6] = t;
          t = st[5]; st[5] = st[7]; st[7] = t; }
    { u64 t = st[2]; st[2] = st[3]; st[3] = t;
          t = st[6]; st[6] = st[7]; st[7] = t; }
#pragma unroll
    for (int k = 1; k < 8; k += 2) {
        float a, bb; unpack2(st[k], a, bb);
        st[k] = pack2(bb, a);
    }
#pragma unroll
    for (int k = 0; k < 8; ++k) {
        float a, bb; unpack2(st[k], a, bb);
        bb = __shfl_xor_sync(FULL_MASK, bb, 24);
        st[k] = pack2(a, bb);
    }
}

// Encoding + product state (layer-0 RYs and CNOT ring folded in)
__device__ __forceinline__ void buildState(
    u64* st, const float* __restrict__ x, const float (*s_h0)[9],
    int b, int shh, int sw, int c, int lane
) {
    float ec[9], es[9];
#pragma unroll
    for (int q = 0; q < 9; ++q) {
        const int di = q / 3 - 1, dj = q % 3 - 1;
        const int hi = shh + di, wj = sw + dj;
        float px = 0.0f;
        if ((unsigned)hi < 32u && (unsigned)wj < 32u)
            px = x[((b * 32 + hi) * 32 + wj) * 3 + c];
        __sincosf(fmaf(1.5707963267948966f, px, s_h0[c][q]), &es[q], &ec[q]);
    }
    const int c0 = (lane >> 4) & 1, c1 = (lane >> 3) & 1, c2 = (lane >> 2) & 1,
              c3 = (lane >> 1) & 1, c4 = lane & 1;
    const float Pb = ((c2 ^ c1) ? es[2] : ec[2]) * ((c3 ^ c2) ? es[3] : ec[3]) *
                     ((c4 ^ c3) ? es[4] : ec[4]);
    const float P0 = Pb * (c0 ? es[0] : ec[0]) * ((c1 ^ c0) ? es[1] : ec[1]); // q8=0
    const float P1 = Pb * (c0 ? ec[0] : es[0]) * ((c1 ^ c0) ? ec[1] : es[1]); // q8=1
    const float G0 = c4 ? es[5] : ec[5];
    const float G1 = c4 ? ec[5] : es[5];
    const u64 PP  = pack2(P0, P1);
    const u64 T8a = pack2(ec[8], es[8]);
    const u64 T8b = pack2(es[8], ec[8]);
#pragma unroll
    for (int k = 0; k < 8; ++k) {
        const int k2 = (k >> 2) & 1, k1 = (k >> 1) & 1, k0 = k & 1;
        const float m = (k2 ? G1 : G0) * ((k1 ^ k2) ? es[6] : ec[6]) *
                        ((k0 ^ k1) ? es[7] : ec[7]);
        st[k] = mul2(mul2(PP, pack2(m, m)), k0 ? T8b : T8a);
    }
}

// Measurement: layer-2 CNOT ring conjugated into diagonal Pauli strings.
__device__ __forceinline__ void measure(
    const u64* st, int lam, float& z0, float& z1, float& z2
) {
    u64 accE = 0ull, accO = 0ull;
#pragma unroll
    for (int k = 0; k < 8; ++k) {
        const u64 p = mul2(st[k], st[k]);
        if ((0x69 >> k) & 1) accE = add2(accE, p);
        else                 accO = add2(accO, p);
    }
    float e0, e1, o0, o1;
    unpack2(accE, e0, e1); unpack2(accO, o0, o1);
    const float sp = e0 + o1, sm = e1 + o0;
    const float tot = sp + sm;
    const float dif = sp - sm;

    float u = (__popc(lam & 0x0F) & 1) ? -dif : dif;
    u += __shfl_xor_sync(FULL_MASK, u, 16);
    u += __shfl_xor_sync(FULL_MASK, u, 8);
    u += __shfl_xor_sync(FULL_MASK, u, 4);
    u += __shfl_xor_sync(FULL_MASK, u, 2);
    u += __shfl_xor_sync(FULL_MASK, u, 1);

    float y = (__popc(lam & 0x18) & 1) ? -tot : tot;
    y += __shfl_xor_sync(FULL_MASK, y, 1);
    y += __shfl_xor_sync(FULL_MASK, y, 2);
    y += __shfl_xor_sync(FULL_MASK, y, 12);
    y += __shfl_xor_sync(FULL_MASK, y, 20);
    const float w = __shfl_xor_sync(FULL_MASK, y, 4);

    z0 = u; z1 = y + w; z2 = y - w;   // lam(0)=0 -> bit2-class 0 at lane 0
}

// Persistent kernel: 1332 blocks (148 SM x 9 resident) x 128 threads = 5328
// warps, grid-striding over 12288 site-pair units (2 sites each, adjacent w,
// same channel). Two independent dependency chains per unit fill SHFL stalls;
// per-SM unit counts are equalized (~83/SM), killing wave quantization.
__global__ void __launch_bounds__(128, 9)
quanv_main(const float* __restrict__ x, const float* __restrict__ qp,
           float* __restrict__ out) {
    __shared__ float s_vc[2][3][9], s_vs[2][3][9], s_h0[3][9];

    const int tid = threadIdx.x;

    // ---- per-block prep ----
    if (tid < 27) {
        int cc = tid / 9, q = tid % 9;
        s_h0[cc][q] = 0.5f * qp[cc * 16 + q];
    } else if (tid < 81) {
        int u = tid - 27;
        int l = u / 27;
        int cc = (u % 27) / 9;
        int q = u % 9;
        float s, co;
        __sincosf(0.5f * qp[((l + 1) * 3 + cc) * 16 + q], &s, &co);
        s_vc[l][cc][q] = co;
        s_vs[l][cc][q] = s;
    }
    __syncthreads();

    const int lane = tid & 31;
    const int warp0 = (blockIdx.x * 128 + tid) >> 5;   // 0..5327
    const int lam = lane ^ (lane >> 1) ^ (lane >> 2) ^ (lane >> 3) ^ (lane >> 4);
    const bool hiRing = (__popc(lane) & 1) != 0;

    for (int unit = warp0; unit < 12288; unit += 5328) {
        const int c   = unit % 3;
        const int wp  = (unit / 3) & 15;
        const int shh = (unit / 48) & 31;
        const int b   = unit / 1536;
        const int swA = 2 * wp;
        const int siteA = ((b * 32 + shh) * 32 + swA) * 3 + c;   // flat (b,h,w,c)

        u64 sA[8], sB[8];
        buildState(sA, x, s_h0, b, shh, swA,     c, lane);
        buildState(sB, x, s_h0, b, shh, swA + 1, c, lane);

        // ================= Layer 1 =================
#pragma unroll
        for (int q = 0; q < 5; ++q) {                 // lane RYs (plain masks)
            const int m = 1 << (4 - q);
            const float vc = s_vc[0][c][q], vs = s_vs[0][c][q];
            const float svs = (lane & m) ? vs : -vs;
            const u64 vc2 = pack2(vc, vc), svs2 = pack2(svs, svs);
            laneRY(sA, m, vc2, svs2);
            laneRY(sB, m, vc2, svs2);
        }
#pragma unroll
        for (int q = 5; q < 8; ++q) {                 // reg RYs
            const int m2 = 1 << (7 - q);
            const float vc = s_vc[0][c][q], vs = s_vs[0][c][q];
            const u64 vc2 = pack2(vc, vc), vsp = pack2(vs, vs), vsn = pack2(-vs, -vs);
            regRY(sA, m2, vc2, vsp, vsn);
            regRY(sB, m2, vc2, vsp, vsn);
        }
        {                                             // pair RY q8
            const float vc = s_vc[0][c][8], vs = s_vs[0][c][8];
            const u64 vc2 = pack2(vc, vc), vspm = pack2(-vs, vs);
            pairRY(sA, vc2, vspm);
            pairRY(sB, vc2, vspm);
        }
        ringTail(sA, hiRing);                         // CNOT ring tail
        ringTail(sB, hiRing);

        // ============ Layer 2 (deferred-permutation space) ============
        {
            const int pmask[5] = {24, 12, 6, 3, 1};
#pragma unroll
            for (int q = 0; q < 5; ++q) {
                const int lm = 1 << (4 - q);
                const int pm = pmask[q];
                const float vc = s_vc[1][c][q], vs = s_vs[1][c][q];
                const float svs = (lam & lm) ? vs : -vs;
                const u64 vc2 = pack2(vc, vc), svs2 = pack2(svs, svs);
                laneRY(sA, pm, vc2, svs2);
                laneRY(sB, pm, vc2, svs2);
            }
        }
#pragma unroll
        for (int q = 5; q < 8; ++q) {
            const int m2 = 1 << (7 - q);
            const float vc = s_vc[1][c][q], vs = s_vs[1][c][q];
            const u64 vc2 = pack2(vc, vc), vsp = pack2(vs, vs), vsn = pack2(-vs, -vs);
            regRY(sA, m2, vc2, vsp, vsn);
            regRY(sB, m2, vc2, vsp, vsn);
        }
        {
            const float vc = s_vc[1][c][8], vs = s_vs[1][c][8];
            const u64 vc2 = pack2(vc, vc), vspm = pack2(-vs, vs);
            pairRY(sA, vc2, vspm);
            pairRY(sB, vc2, vspm);
        }

        // ================= Measurement =================
        float a0, a1, a2, b0, b1, b2;
        measure(sA, lam, a0, a1, a2);
        measure(sB, lam, b0, b1, b2);
        if (lane == 0) {
            // site B at w+1: site index +3 (channel stride) -> out offset +9.
            out[3 * siteA + 0]  = a0;
            out[3 * siteA + 1]  = a1;
            out[3 * siteA + 2]  = a2;
            out[3 * siteA + 9]  = b0;
            out[3 * siteA + 10] = b1;
            out[3 * siteA + 11] = b2;
        }
    }
}

extern "C" void kernel_launch(void* const* d_in, const int* in_sizes, int n_in,
                              void* d_out, int out_size) {
    const float* x  = (const float*)d_in[0];
    const float* qp = (const float*)d_in[1];
    float* out = (float*)d_out;
    // 148 SMs x 9 resident blocks = 1332 persistent blocks, 128 threads each.
    quanv_main<<<1332, 128>>>(x, qp, out);
}

// round 11
// speedup vs baseline: 1.2276x; 1.2276x over previous
#include <cuda_runtime.h>

#define FULL_MASK 0xFFFFFFFFu
typedef unsigned long long u64;

// ---------- packed f32x2 helpers (sm_100a) ----------
__device__ __forceinline__ u64 pack2(float a, float b) {
    u64 d; asm("mov.b64 %0, {%1, %2};" : "=l"(d) : "f"(a), "f"(b)); return d;
}
__device__ __forceinline__ void unpack2(u64 v, float& a, float& b) {
    asm("mov.b64 {%0, %1}, %2;" : "=f"(a), "=f"(b) : "l"(v));
}
__device__ __forceinline__ u64 fma2(u64 a, u64 b, u64 c) {
    u64 d; asm("fma.rn.f32x2 %0, %1, %2, %3;" : "=l"(d) : "l"(a), "l"(b), "l"(c)); return d;
}
__device__ __forceinline__ u64 mul2(u64 a, u64 b) {
    u64 d; asm("mul.rn.f32x2 %0, %1, %2;" : "=l"(d) : "l"(a), "l"(b)); return d;
}
__device__ __forceinline__ u64 add2(u64 a, u64 b) {
    u64 d; asm("add.rn.f32x2 %0, %1, %2;" : "=l"(d) : "l"(a), "l"(b)); return d;
}

// 16-lane-per-site layout. Warp = 2 sites (lane bit4 = site s; l4 = lane&15).
// Per-thread state: 16 f32x2 regs. Amp index i = l4*32 + k*2 + p:
//   q0..q3 <-> l4 bits 3..0, q4..q7 <-> k bits 3..0, q8 <-> pair bit p.
// Layer-1 CNOT chain q0->1->2->3 (all lane bits) is DEFERRED: physical lane l
// holds logical lam4(l) = l^(l>>1)^(l>>2)^(l>>3) (4-bit); logical xor-m
// butterflies become physical shfl_xor with pi(m) = m^(m>>1).
__global__ void __launch_bounds__(128, 8)
quanv_main(const float* __restrict__ x, const float* __restrict__ qp,
           float* __restrict__ out) {
    __shared__ float s_vc[2][3][9], s_vs[2][3][9], s_h0[3][9];

    const int tid = threadIdx.x;

    // ---- per-block prep: variational cos/sin + folded layer-0 half-angles ----
    if (tid < 27) {
        int cc = tid / 9, q = tid % 9;
        s_h0[cc][q] = 0.5f * qp[cc * 16 + q];
    } else if (tid < 81) {
        int u = tid - 27;
        int l = u / 27;
        int cc = (u % 27) / 9;
        int q = u % 9;
        float s, co;
        __sincosf(0.5f * qp[((l + 1) * 3 + cc) * 16 + q], &s, &co);
        s_vc[l][cc][q] = co;
        s_vs[l][cc][q] = s;
    }
    __syncthreads();

    const int lane = tid & 31;
    const int l4   = lane & 15;
    const int s    = lane >> 4;                       // site within pair
    const int unit = (blockIdx.x * 128 + tid) >> 5;   // 0..12287
    const int c   = unit % 3;
    const int wp  = (unit / 3) & 15;
    const int shh = (unit / 48) & 31;
    const int b   = unit / 1536;
    const int swA = 2 * wp;
    const int sw  = swA + s;                          // this half's w
    const int siteA = ((b * 32 + shh) * 32 + swA) * 3 + c;   // flat (b,h,w,c)

    // --- Encoding RY(pi*px) with layer-0 variational RY folded in ---
    // Each half-warp computes only its own site's 9 sincos.
    float ec[9], es[9];
#pragma unroll
    for (int q = 0; q < 9; ++q) {
        const int di = q / 3 - 1, dj = q % 3 - 1;
        const int hi = shh + di, wj = sw + dj;
        float px = 0.0f;
        if ((unsigned)hi < 32u && (unsigned)wj < 32u)
            px = x[((b * 32 + hi) * 32 + wj) * 3 + c];
        __sincosf(fmaf(1.5707963267948966f, px, s_h0[c][q]), &es[q], &ec[q]);
    }

    // --- Product state with layer-0 CNOT ring folded in (GF(2) index map):
    // b0=c0^c8, b1=c1^c0^c8, bq=cq^c(q-1). c0..c3 = l4 bits 3..0,
    // c4..c7 = k bits 3..0, c8 = p. ---
    const int c0 = (l4 >> 3) & 1, c1 = (l4 >> 2) & 1,
              c2 = (l4 >> 1) & 1, c3 = l4 & 1;
    const float L2 = ((c2 ^ c1) ? es[2] : ec[2]) * ((c3 ^ c2) ? es[3] : ec[3]);
    const float A0 = (c0 ? es[0] : ec[0]) * ((c1 ^ c0) ? es[1] : ec[1]); // c8=0
    const float A1 = (c0 ? ec[0] : es[0]) * ((c1 ^ c0) ? ec[1] : es[1]); // c8=1
    const float G0 = c3 ? es[4] : ec[4];   // k3=0: b4=c3
    const float G1 = c3 ? ec[4] : es[4];   // k3=1: b4=c3^1
    const u64 PP  = pack2(L2 * A0, L2 * A1);
    const u64 T8a = pack2(ec[8], es[8]);   // k0=0: b8=p
    const u64 T8b = pack2(es[8], ec[8]);   // k0=1: b8=p^1

    u64 st[16];
#pragma unroll
    for (int k = 0; k < 16; ++k) {
        const int k3 = (k >> 3) & 1, k2 = (k >> 2) & 1,
                  k1 = (k >> 1) & 1, k0 = k & 1;
        const float m = (k3 ? G1 : G0) * ((k2 ^ k3) ? es[5] : ec[5]) *
                        ((k1 ^ k2) ? es[6] : ec[6]) * ((k0 ^ k1) ? es[7] : ec[7]);
        st[k] = mul2(mul2(PP, pack2(m, m)), k0 ? T8b : T8a);
    }

    const int lam4 = l4 ^ (l4 >> 1) ^ (l4 >> 2) ^ (l4 >> 3);

    // ================= Layer 1 (plain basis) =================
    // lane RYs q0..q3 (masks 8,4,2,1; both sites in one pass)
#pragma unroll
    for (int q = 0; q < 4; ++q) {
        const int m = 8 >> q;
        const float vc = s_vc[0][c][q], vs = s_vs[0][c][q];
        const float svs = (l4 & m) ? vs : -vs;
        const u64 vc2 = pack2(vc, vc), svs2 = pack2(svs, svs);
#pragma unroll
        for (int k = 0; k < 16; ++k) {
            float a, bb; unpack2(st[k], a, bb);
            const float pa = __shfl_xor_sync(FULL_MASK, a, m);
            const float pb = __shfl_xor_sync(FULL_MASK, bb, m);
            st[k] = fma2(vc2, st[k], mul2(svs2, pack2(pa, pb)));
        }
    }
    // reg RYs q4..q7 (k masks 8,4,2,1)
#pragma unroll
    for (int q = 4; q < 8; ++q) {
        const int m2 = 1 << (7 - q);
        const float vc = s_vc[0][c][q], vs = s_vs[0][c][q];
        const u64 vc2 = pack2(vc, vc), vsp = pack2(vs, vs), vsn = pack2(-vs, -vs);
#pragma unroll
        for (int k = 0; k < 16; ++k)
            if (!(k & m2)) {
                const u64 a = st[k], bb = st[k + m2];
                st[k]      = fma2(vc2, a,  mul2(vsn, bb));
                st[k + m2] = fma2(vc2, bb, mul2(vsp, a));
            }
    }
    // pair RY q8
    {
        const float vc = s_vc[0][c][8], vs = s_vs[0][c][8];
        const u64 vc2 = pack2(vc, vc), vspm = pack2(-vs, vs);
#pragma unroll
        for (int k = 0; k < 16; ++k) {
            float a, bb; unpack2(st[k], a, bb);
            st[k] = fma2(vc2, st[k], mul2(vspm, pack2(bb, a)));
        }
    }

    // --- Layer-1 CNOT ring ---
    // q0->1->2->3 lane segment: DEFERRED (logical relabeling).
    // q3->q4: ctrl = logical lane bit0 = popc(l4)&1; tgt k bit 3.
    {
        const bool hi = (__popc(l4) & 1) != 0;
#pragma unroll
        for (int k = 0; k < 8; ++k) {
            const u64 a = st[k], bb = st[k + 8];
            st[k]     = hi ? bb : a;
            st[k + 8] = hi ? a : bb;
        }
    }
    // q4->5 (ctrl k3, tgt k2), q5->6 (k2->k1), q6->7 (k1->k0): renames (free)
    { u64 t;
      t = st[ 8]; st[ 8] = st[12]; st[12] = t;
      t = st[ 9]; st[ 9] = st[13]; st[13] = t;
      t = st[10]; st[10] = st[14]; st[14] = t;
      t = st[11]; st[11] = st[15]; st[15] = t; }
    { u64 t;
      t = st[ 4]; st[ 4] = st[ 6]; st[ 6] = t;
      t = st[ 5]; st[ 5] = st[ 7]; st[ 7] = t;
      t = st[12]; st[12] = st[14]; st[14] = t;
      t = st[13]; st[13] = st[15]; st[15] = t; }
    { u64 t;
      t = st[ 2]; st[ 2] = st[ 3]; st[ 3] = t;
      t = st[ 6]; st[ 6] = st[ 7]; st[ 7] = t;
      t = st[10]; st[10] = st[11]; st[11] = t;
      t = st[14]; st[14] = st[15]; st[15] = t; }
    // q7->q8: ctrl k0, tgt pair: half-swap odd-k vecs
#pragma unroll
    for (int k = 1; k < 16; k += 2) {
        float a, bb; unpack2(st[k], a, bb);
        st[k] = pack2(bb, a);
    }
    // q8->q0: p=1 halves flip logical lane bit3 -> physical mask pi(8)=12
#pragma unroll
    for (int k = 0; k < 16; ++k) {
        float a, bb; unpack2(st[k], a, bb);
        bb = __shfl_xor_sync(FULL_MASK, bb, 12);
        st[k] = pack2(a, bb);
    }

    // ========== Layer 2 (deferred-permutation space) ==========
    // lane RYs: logical masks {8,4,2,1} -> physical {12,6,3,1}; sign lam4&m.
    {
        const int pmask[4] = {12, 6, 3, 1};
#pragma unroll
        for (int q = 0; q < 4; ++q) {
            const int lm = 8 >> q;
            const int pm = pmask[q];
            const float vc = s_vc[1][c][q], vs = s_vs[1][c][q];
            const float svs = (lam4 & lm) ? vs : -vs;
            const u64 vc2 = pack2(vc, vc), svs2 = pack2(svs, svs);
#pragma unroll
            for (int k = 0; k < 16; ++k) {
                float a, bb; unpack2(st[k], a, bb);
                const float pa = __shfl_xor_sync(FULL_MASK, a, pm);
                const float pb = __shfl_xor_sync(FULL_MASK, bb, pm);
                st[k] = fma2(vc2, st[k], mul2(svs2, pack2(pa, pb)));
            }
        }
    }
#pragma unroll
    for (int q = 4; q < 8; ++q) {
        const int m2 = 1 << (7 - q);
        const float vc = s_vc[1][c][q], vs = s_vs[1][c][q];
        const u64 vc2 = pack2(vc, vc), vsp = pack2(vs, vs), vsn = pack2(-vs, -vs);
#pragma unroll
        for (int k = 0; k < 16; ++k)
            if (!(k & m2)) {
                const u64 a = st[k], bb = st[k + m2];
                st[k]      = fma2(vc2, a,  mul2(vsn, bb));
                st[k + m2] = fma2(vc2, bb, mul2(vsp, a));
            }
    }
    {
        const float vc = s_vc[1][c][8], vs = s_vs[1][c][8];
        const u64 vc2 = pack2(vc, vc), vspm = pack2(-vs, vs);
#pragma unroll
        for (int k = 0; k < 16; ++k) {
            float a, bb; unpack2(st[k], a, bb);
            st[k] = fma2(vc2, st[k], mul2(vspm, pack2(bb, a)));
        }
    }

    // --- Measurement: layer-2 ring conjugated into diagonal Pauli strings.
    // Amp bits: [lam3 lam2 lam1 lam0 | k3 k2 k1 k0 | p].
    // Z0 -> parity(bits 7..0) = popc(lam4&7) ^ popc(k) ^ p
    // Z1 -> parity(bits 8,7)  = popc(lam4&12)
    // Z2 -> parity(bits 8..6) = popc(lam4&12) ^ lam1 (class trick). ---
    u64 accE = 0ull, accO = 0ull;
#pragma unroll
    for (int k = 0; k < 16; ++k) {
        const u64 p = mul2(st[k], st[k]);
        if ((0x9669 >> k) & 1) accE = add2(accE, p);   // popc(k) even
        else                   accO = add2(accO, p);
    }
    float e0, e1, o0, o1;
    unpack2(accE, e0, e1); unpack2(accO, o0, o1);
    const float sp = e0 + o1, sm = e1 + o0;
    const float tot = sp + sm;
    const float dif = sp - sm;

    // z0: per-half 4-level reduce (masks stay within the 16-lane half)
    float u = (__popc(lam4 & 7) & 1) ? -dif : dif;
    u += __shfl_xor_sync(FULL_MASK, u, 8);
    u += __shfl_xor_sync(FULL_MASK, u, 4);
    u += __shfl_xor_sync(FULL_MASK, u, 2);
    u += __shfl_xor_sync(FULL_MASK, u, 1);

    // z1/z2 factored: reduce y over the lam1-preserving subgroup span{1,6,10}
    // (8 physical lanes/class), then one cross-class shuffle (mask 2).
    float y = (__popc(lam4 & 12) & 1) ? -tot : tot;
    y += __shfl_xor_sync(FULL_MASK, y, 1);
    y += __shfl_xor_sync(FULL_MASK, y, 6);
    y += __shfl_xor_sync(FULL_MASK, y, 10);
    const float w = __shfl_xor_sync(FULL_MASK, y, 2);

    if (l4 == 0) {                       // lanes 0 (site A) and 16 (site B)
        const int base = 3 * siteA + 9 * s;   // site index +3 per w -> +9 floats
        out[base + 0] = u;
        out[base + 1] = y + w;           // lam4(0)=0 -> lam1-class 0
        out[base + 2] = y - w;
    }
}

extern "C" void kernel_launch(void* const* d_in, const int* in_sizes, int n_in,
                              void* d_out, int out_size) {
    const float* x  = (const float*)d_in[0];
    const float* qp = (const float*)d_in[1];
    float* out = (float*)d_out;
    // 12288 site-pair warps / 4 warps per 128-thread block = 3072 blocks
    quanv_main<<<3072, 128>>>(x, qp, out);
}

// round 12
// speedup vs baseline: 1.4420x; 1.1746x over previous
#include <cuda_runtime.h>

#define FULL_MASK 0xFFFFFFFFu
typedef unsigned long long u64;

// ---------- packed f32x2 helpers (sm_100a) ----------
__device__ __forceinline__ u64 pack2(float a, float b) {
    u64 d; asm("mov.b64 %0, {%1, %2};" : "=l"(d) : "f"(a), "f"(b)); return d;
}
__device__ __forceinline__ void unpack2(u64 v, float& a, float& b) {
    asm("mov.b64 {%0, %1}, %2;" : "=f"(a), "=f"(b) : "l"(v));
}
__device__ __forceinline__ u64 fma2(u64 a, u64 b, u64 c) {
    u64 d; asm("fma.rn.f32x2 %0, %1, %2, %3;" : "=l"(d) : "l"(a), "l"(b), "l"(c)); return d;
}
__device__ __forceinline__ u64 mul2(u64 a, u64 b) {
    u64 d; asm("mul.rn.f32x2 %0, %1, %2;" : "=l"(d) : "l"(a), "l"(b)); return d;
}
__device__ __forceinline__ u64 add2(u64 a, u64 b) {
    u64 d; asm("add.rn.f32x2 %0, %1, %2;" : "=l"(d) : "l"(a), "l"(b)); return d;
}

// 16-lane-per-site layout. Warp = 2 sites (lane bit4 = site s; l4 = lane&15).
// Per-thread state: 16 f32x2 regs. Amp index i = l4*32 + k*2 + p:
//   q0..q3 <-> l4 bits 3..0, q4..q7 <-> k bits 3..0, q8 <-> pair bit p.
// Layer-1 CNOT chain q0->1->2->3 is DEFERRED (logical lam4 = 4-bit prefix-xor).
// Variational RYs use TANGENT FORM: RY(th) = cos th * [[1,-t],[t,1]]; the
// 18 cos factors fold into one per-channel scalar S, applied as S^2 to the
// probabilities at measurement.
__global__ void __launch_bounds__(128, 8)
quanv_main(const float* __restrict__ x, const float* __restrict__ qp,
           float* __restrict__ out) {
    __shared__ float s_vt[2][3][9];   // tan(theta/2) for layers 1,2
    __shared__ float s_h0[3][9];      // folded layer-0 half-angles
    __shared__ float s_s2[3];         // (prod cos)^2 per channel

    const int tid = threadIdx.x;

    // ---- per-block prep ----
    if (tid < 27) {
        int cc = tid / 9, q = tid % 9;
        s_h0[cc][q] = 0.5f * qp[cc * 16 + q];
    } else if (tid < 81) {
        int u = tid - 27;
        int l = u / 27;                         // 0 -> qp layer 1, 1 -> layer 2
        int cc = (u % 27) / 9;
        int q = u % 9;
        float s, co;
        __sincosf(0.5f * qp[((l + 1) * 3 + cc) * 16 + q], &s, &co);
        s_vt[l][cc][q] = __fdividef(s, co);
    } else if (tid < 84) {
        int cc = tid - 81;
        float p = 1.0f;
#pragma unroll
        for (int l = 1; l <= 2; ++l)
#pragma unroll
            for (int q = 0; q < 9; ++q)
                p *= __cosf(0.5f * qp[(l * 3 + cc) * 16 + q]);
        s_s2[cc] = p * p;
    }
    __syncthreads();

    const int lane = tid & 31;
    const int l4   = lane & 15;
    const int s    = lane >> 4;                       // site within pair
    const int unit = (blockIdx.x * 128 + tid) >> 5;   // 0..12287
    const int c   = unit % 3;
    const int wp  = (unit / 3) & 15;
    const int shh = (unit / 48) & 31;
    const int b   = unit / 1536;
    const int swA = 2 * wp;
    const int sw  = swA + s;
    const int siteA = ((b * 32 + shh) * 32 + swA) * 3 + c;   // flat (b,h,w,c)

    // --- Encoding RY(pi*px) with layer-0 variational RY folded in ---
    float ec[9], es[9];
#pragma unroll
    for (int q = 0; q < 9; ++q) {
        const int di = q / 3 - 1, dj = q % 3 - 1;
        const int hi = shh + di, wj = sw + dj;
        float px = 0.0f;
        if ((unsigned)hi < 32u && (unsigned)wj < 32u)
            px = x[((b * 32 + hi) * 32 + wj) * 3 + c];
        __sincosf(fmaf(1.5707963267948966f, px, s_h0[c][q]), &es[q], &ec[q]);
    }

    // --- Product state with layer-0 CNOT ring folded in (GF(2) index map) ---
    const int c0 = (l4 >> 3) & 1, c1 = (l4 >> 2) & 1,
              c2 = (l4 >> 1) & 1, c3 = l4 & 1;
    const float L2 = ((c2 ^ c1) ? es[2] : ec[2]) * ((c3 ^ c2) ? es[3] : ec[3]);
    const float A0 = (c0 ? es[0] : ec[0]) * ((c1 ^ c0) ? es[1] : ec[1]); // c8=0
    const float A1 = (c0 ? ec[0] : es[0]) * ((c1 ^ c0) ? ec[1] : es[1]); // c8=1
    const float G0 = c3 ? es[4] : ec[4];
    const float G1 = c3 ? ec[4] : es[4];
    const u64 PP  = pack2(L2 * A0, L2 * A1);
    const u64 T8a = pack2(ec[8], es[8]);
    const u64 T8b = pack2(es[8], ec[8]);

    u64 st[16];
#pragma unroll
    for (int k = 0; k < 16; ++k) {
        const int k3 = (k >> 3) & 1, k2 = (k >> 2) & 1,
                  k1 = (k >> 1) & 1, k0 = k & 1;
        const float m = (k3 ? G1 : G0) * ((k2 ^ k3) ? es[5] : ec[5]) *
                        ((k1 ^ k2) ? es[6] : ec[6]) * ((k0 ^ k1) ? es[7] : ec[7]);
        st[k] = mul2(mul2(PP, pack2(m, m)), k0 ? T8b : T8a);
    }

    const int lam4 = l4 ^ (l4 >> 1) ^ (l4 >> 2) ^ (l4 >> 3);

    // ================= Layer 1 (plain basis, tangent form) =================
    // lane RYs q0..q3: st' = st + (sign*t)*partner   (cos deferred)
#pragma unroll
    for (int q = 0; q < 4; ++q) {
        const int m = 8 >> q;
        const float t = s_vt[0][c][q];
        const float sts = (l4 & m) ? t : -t;
        const u64 t2 = pack2(sts, sts);
#pragma unroll
        for (int k = 0; k < 16; ++k) {
            float a, bb; unpack2(st[k], a, bb);
            const float pa = __shfl_xor_sync(FULL_MASK, a, m);
            const float pb = __shfl_xor_sync(FULL_MASK, bb, m);
            st[k] = fma2(t2, pack2(pa, pb), st[k]);
        }
    }
    // reg RYs q4..q7: a' = a - t*b ; b' = b + t*a
#pragma unroll
    for (int q = 4; q < 8; ++q) {
        const int m2 = 1 << (7 - q);
        const float t = s_vt[0][c][q];
        const u64 tp = pack2(t, t), tn = pack2(-t, -t);
#pragma unroll
        for (int k = 0; k < 16; ++k)
            if (!(k & m2)) {
                const u64 a = st[k], bb = st[k + m2];
                st[k]      = fma2(tn, bb, a);
                st[k + m2] = fma2(tp, a, bb);
            }
    }
    // pair RY q8: st' = st + (-t,+t)*swap(st)
    {
        const float t = s_vt[0][c][8];
        const u64 tpm = pack2(-t, t);
#pragma unroll
        for (int k = 0; k < 16; ++k) {
            float a, bb; unpack2(st[k], a, bb);
            st[k] = fma2(tpm, pack2(bb, a), st[k]);
        }
    }

    // --- Layer-1 CNOT ring ---
    // q0..q3 lane segment: DEFERRED. q3->q4: ctrl = popc(l4)&1, tgt k bit 3.
    {
        const bool hi = (__popc(l4) & 1) != 0;
#pragma unroll
        for (int k = 0; k < 8; ++k) {
            const u64 a = st[k], bb = st[k + 8];
            st[k]     = hi ? bb : a;
            st[k + 8] = hi ? a : bb;
        }
    }
    // q4->5, q5->6, q6->7: register renames (free)
    { u64 t;
      t = st[ 8]; st[ 8] = st[12]; st[12] = t;
      t = st[ 9]; st[ 9] = st[13]; st[13] = t;
      t = st[10]; st[10] = st[14]; st[14] = t;
      t = st[11]; st[11] = st[15]; st[15] = t; }
    { u64 t;
      t = st[ 4]; st[ 4] = st[ 6]; st[ 6] = t;
      t = st[ 5]; st[ 5] = st[ 7]; st[ 7] = t;
      t = st[12]; st[12] = st[14]; st[14] = t;
      t = st[13]; st[13] = st[15]; st[15] = t; }
    { u64 t;
      t = st[ 2]; st[ 2] = st[ 3]; st[ 3] = t;
      t = st[ 6]; st[ 6] = st[ 7]; st[ 7] = t;
      t = st[10]; st[10] = st[11]; st[11] = t;
      t = st[14]; st[14] = st[15]; st[15] = t; }
    // q7->q8: half-swap odd-k vecs
#pragma unroll
    for (int k = 1; k < 16; k += 2) {
        float a, bb; unpack2(st[k], a, bb);
        st[k] = pack2(bb, a);
    }
    // q8->q0: p=1 halves flip logical lane bit3 -> physical mask pi(8)=12
#pragma unroll
    for (int k = 0; k < 16; ++k) {
        float a, bb; unpack2(st[k], a, bb);
        bb = __shfl_xor_sync(FULL_MASK, bb, 12);
        st[k] = pack2(a, bb);
    }

    // ========== Layer 2 (deferred space, tangent form) ==========
    {
        const int pmask[4] = {12, 6, 3, 1};
#pragma unroll
        for (int q = 0; q < 4; ++q) {
            const int lm = 8 >> q;
            const int pm = pmask[q];
            const float t = s_vt[1][c][q];
            const float sts = (lam4 & lm) ? t : -t;
            const u64 t2 = pack2(sts, sts);
#pragma unroll
            for (int k = 0; k < 16; ++k) {
                float a, bb; unpack2(st[k], a, bb);
                const float pa = __shfl_xor_sync(FULL_MASK, a, pm);
                const float pb = __shfl_xor_sync(FULL_MASK, bb, pm);
                st[k] = fma2(t2, pack2(pa, pb), st[k]);
            }
        }
    }
#pragma unroll
    for (int q = 4; q < 8; ++q) {
        const int m2 = 1 << (7 - q);
        const float t = s_vt[1][c][q];
        const u64 tp = pack2(t, t), tn = pack2(-t, -t);
#pragma unroll
        for (int k = 0; k < 16; ++k)
            if (!(k & m2)) {
                const u64 a = st[k], bb = st[k + m2];
                st[k]      = fma2(tn, bb, a);
                st[k + m2] = fma2(tp, a, bb);
            }
    }
    {
        const float t = s_vt[1][c][8];
        const u64 tpm = pack2(-t, t);
#pragma unroll
        for (int k = 0; k < 16; ++k) {
            float a, bb; unpack2(st[k], a, bb);
            st[k] = fma2(tpm, pack2(bb, a), st[k]);
        }
    }

    // --- Measurement (diagonal Pauli strings; cos product restored as S^2) ---
    u64 accE = 0ull, accO = 0ull;
#pragma unroll
    for (int k = 0; k < 16; ++k) {
        const u64 p = mul2(st[k], st[k]);
        if ((0x9669 >> k) & 1) accE = add2(accE, p);   // popc(k) even
        else                   accO = add2(accO, p);
    }
    float e0, e1, o0, o1;
    unpack2(accE, e0, e1); unpack2(accO, o0, o1);
    const float s2 = s_s2[c];
    const float sp = e0 + o1, sm = e1 + o0;
    const float tot = (sp + sm) * s2;
    const float dif = (sp - sm) * s2;

    // z0: per-half 4-level reduce
    float u = (__popc(lam4 & 7) & 1) ? -dif : dif;
    u += __shfl_xor_sync(FULL_MASK, u, 8);
    u += __shfl_xor_sync(FULL_MASK, u, 4);
    u += __shfl_xor_sync(FULL_MASK, u, 2);
    u += __shfl_xor_sync(FULL_MASK, u, 1);

    // z1/z2 factored: reduce over lam1-class subgroup {1,6,10}, cross mask 2
    float y = (__popc(lam4 & 12) & 1) ? -tot : tot;
    y += __shfl_xor_sync(FULL_MASK, y, 1);
    y += __shfl_xor_sync(FULL_MASK, y, 6);
    y += __shfl_xor_sync(FULL_MASK, y, 10);
    const float w = __shfl_xor_sync(FULL_MASK, y, 2);

    if (l4 == 0) {                       // lanes 0 (site A) and 16 (site B)
        const int base = 3 * siteA + 9 * s;
        out[base + 0] = u;
        out[base + 1] = y + w;           // lam4(0)=0 -> lam1-class 0
        out[base + 2] = y - w;
    }
}

extern "C" void kernel_launch(void* const* d_in, const int* in_sizes, int n_in,
                              void* d_out, int out_size) {
    const float* x  = (const float*)d_in[0];
    const float* qp = (const float*)d_in[1];
    float* out = (float*)d_out;
    // 12288 site-pair warps / 4 warps per 128-thread block = 3072 blocks
    quanv_main<<<3072, 128>>>(x, qp, out);
}

// round 13
// speedup vs baseline: 1.4763x; 1.0237x over previous
#include <cuda_runtime.h>

#define FULL_MASK 0xFFFFFFFFu
typedef unsigned long long u64;

// ---------- packed f32x2 helpers (sm_100a) ----------
__device__ __forceinline__ u64 pack2(float a, float b) {
    u64 d; asm("mov.b64 %0, {%1, %2};" : "=l"(d) : "f"(a), "f"(b)); return d;
}
__device__ __forceinline__ void unpack2(u64 v, float& a, float& b) {
    asm("mov.b64 {%0, %1}, %2;" : "=f"(a), "=f"(b) : "l"(v));
}
__device__ __forceinline__ u64 fma2(u64 a, u64 b, u64 c) {
    u64 d; asm("fma.rn.f32x2 %0, %1, %2, %3;" : "=l"(d) : "l"(a), "l"(b), "l"(c)); return d;
}
__device__ __forceinline__ u64 mul2(u64 a, u64 b) {
    u64 d; asm("mul.rn.f32x2 %0, %1, %2;" : "=l"(d) : "l"(a), "l"(b)); return d;
}
__device__ __forceinline__ u64 add2(u64 a, u64 b) {
    u64 d; asm("add.rn.f32x2 %0, %1, %2;" : "=l"(d) : "l"(a), "l"(b)); return d;
}

// 16-lane-per-site layout. Warp = 2 sites (lane bit4 = site s; l4 = lane&15).
// Per-thread state: 16 f32x2 regs. Amp index i = l4*32 + k*2 + p:
//   q0..q3 <-> l4 bits 3..0, q4..q7 <-> k bits 3..0, q8 <-> pair bit p.
// Layer-1 CNOT chain q0->1->2->3 is DEFERRED (logical lam4 = 4-bit prefix-xor).
// Variational RYs in TANGENT FORM; the 18 cos factors fold into one per-channel
// scalar applied as S^2 at measurement.
// Build is SPLIT in two phases to cut peak register pressure (56-reg cap).
__global__ void __launch_bounds__(128, 9)
quanv_main(const float* __restrict__ x, const float* __restrict__ qp,
           float* __restrict__ out) {
    __shared__ float s_vt[2][3][9];   // tan(theta/2) for layers 1,2
    __shared__ float s_h0[3][9];      // folded layer-0 half-angles
    __shared__ float s_s2[3];         // (prod cos)^2 per channel

    const int tid = threadIdx.x;

    // ---- per-block prep ----
    if (tid < 27) {
        int cc = tid / 9, q = tid % 9;
        s_h0[cc][q] = 0.5f * qp[cc * 16 + q];
    } else if (tid < 81) {
        int u = tid - 27;
        int l = u / 27;                         // 0 -> qp layer 1, 1 -> layer 2
        int cc = (u % 27) / 9;
        int q = u % 9;
        float s, co;
        __sincosf(0.5f * qp[((l + 1) * 3 + cc) * 16 + q], &s, &co);
        s_vt[l][cc][q] = __fdividef(s, co);
    } else if (tid < 84) {
        int cc = tid - 81;
        float p = 1.0f;
#pragma unroll
        for (int l = 1; l <= 2; ++l)
#pragma unroll
            for (int q = 0; q < 9; ++q)
                p *= __cosf(0.5f * qp[(l * 3 + cc) * 16 + q]);
        s_s2[cc] = p * p;
    }
    __syncthreads();

    const int lane = tid & 31;
    const int l4   = lane & 15;
    const int s    = lane >> 4;                       // site within pair
    const int unit = (blockIdx.x * 128 + tid) >> 5;   // 0..12287
    const int c   = unit % 3;
    const int wp  = (unit / 3) & 15;
    const int shh = (unit / 48) & 31;
    const int b   = unit / 1536;
    const int sw  = 2 * wp + s;                       // this half's w

    const int c0 = (l4 >> 3) & 1, c1 = (l4 >> 2) & 1,
              c2 = (l4 >> 1) & 1, c3 = l4 & 1;

    // --- Build phase 1: qubits 0..3 -> per-lane scalar PP (regs die after) ---
    u64 PP;
    {
        float ecl[4], esl[4];
#pragma unroll
        for (int q = 0; q < 4; ++q) {
            const int di = q / 3 - 1, dj = q % 3 - 1;
            const int hi = shh + di, wj = sw + dj;
            float px = 0.0f;
            if ((unsigned)hi < 32u && (unsigned)wj < 32u)
                px = x[((b * 32 + hi) * 32 + wj) * 3 + c];
            __sincosf(fmaf(1.5707963267948966f, px, s_h0[c][q]), &esl[q], &ecl[q]);
        }
        // layer-0 CNOT-ring GF(2) map: b0=c0^c8, b1=c1^c0^c8, bq=cq^c(q-1)
        const float L2 = ((c2 ^ c1) ? esl[2] : ecl[2]) * ((c3 ^ c2) ? esl[3] : ecl[3]);
        const float A0 = (c0 ? esl[0] : ecl[0]) * ((c1 ^ c0) ? esl[1] : ecl[1]); // c8=0
        const float A1 = (c0 ? ecl[0] : esl[0]) * ((c1 ^ c0) ? ecl[1] : esl[1]); // c8=1
        PP = pack2(L2 * A0, L2 * A1);
    }

    // --- Build phase 2: qubits 4..8 -> per-k factors, write state ---
    u64 st[16];
    {
        float ech[5], esh[5];
#pragma unroll
        for (int q = 4; q < 9; ++q) {
            const int di = q / 3 - 1, dj = q % 3 - 1;
            const int hi = shh + di, wj = sw + dj;
            float px = 0.0f;
            if ((unsigned)hi < 32u && (unsigned)wj < 32u)
                px = x[((b * 32 + hi) * 32 + wj) * 3 + c];
            __sincosf(fmaf(1.5707963267948966f, px, s_h0[c][q]), &esh[q - 4], &ech[q - 4]);
        }
        const float G0 = c3 ? esh[0] : ech[0];   // k3=0: b4=c3
        const float G1 = c3 ? ech[0] : esh[0];   // k3=1: b4=c3^1
        const u64 T8a = pack2(ech[4], esh[4]);   // k0=0: b8=p
        const u64 T8b = pack2(esh[4], ech[4]);   // k0=1: b8=p^1
#pragma unroll
        for (int k = 0; k < 16; ++k) {
            const int k3 = (k >> 3) & 1, k2 = (k >> 2) & 1,
                      k1 = (k >> 1) & 1, k0 = k & 1;
            const float m = (k3 ? G1 : G0) * ((k2 ^ k3) ? esh[1] : ech[1]) *
                            ((k1 ^ k2) ? esh[2] : ech[2]) * ((k0 ^ k1) ? esh[3] : ech[3]);
            st[k] = mul2(mul2(PP, pack2(m, m)), k0 ? T8b : T8a);
        }
    }

    const int lam4 = l4 ^ (l4 >> 1) ^ (l4 >> 2) ^ (l4 >> 3);

    // ================= Layer 1 (plain basis, tangent form) =================
    // lane RYs q0..q3: st' = st + (sign*t)*partner   (cos deferred)
#pragma unroll
    for (int q = 0; q < 4; ++q) {
        const int m = 8 >> q;
        const float t = s_vt[0][c][q];
        const float sts = (l4 & m) ? t : -t;
        const u64 t2 = pack2(sts, sts);
#pragma unroll
        for (int k = 0; k < 16; ++k) {
            float a, bb; unpack2(st[k], a, bb);
            const float pa = __shfl_xor_sync(FULL_MASK, a, m);
            const float pb = __shfl_xor_sync(FULL_MASK, bb, m);
            st[k] = fma2(t2, pack2(pa, pb), st[k]);
        }
    }
    // reg RYs q4..q7: a' = a - t*b ; b' = b + t*a
#pragma unroll
    for (int q = 4; q < 8; ++q) {
        const int m2 = 1 << (7 - q);
        const float t = s_vt[0][c][q];
        const u64 tp = pack2(t, t), tn = pack2(-t, -t);
#pragma unroll
        for (int k = 0; k < 16; ++k)
            if (!(k & m2)) {
                const u64 a = st[k], bb = st[k + m2];
                st[k]      = fma2(tn, bb, a);
                st[k + m2] = fma2(tp, a, bb);
            }
    }
    // pair RY q8: st' = st + (-t,+t)*swap(st)
    {
        const float t = s_vt[0][c][8];
        const u64 tpm = pack2(-t, t);
#pragma unroll
        for (int k = 0; k < 16; ++k) {
            float a, bb; unpack2(st[k], a, bb);
            st[k] = fma2(tpm, pack2(bb, a), st[k]);
        }
    }

    // --- Layer-1 CNOT ring ---
    // q0..q3 lane segment: DEFERRED. q3->q4: ctrl = popc(l4)&1, tgt k bit 3.
    {
        const bool hi = (__popc(l4) & 1) != 0;
#pragma unroll
        for (int k = 0; k < 8; ++k) {
            const u64 a = st[k], bb = st[k + 8];
            st[k]     = hi ? bb : a;
            st[k + 8] = hi ? a : bb;
        }
    }
    // q4->5, q5->6, q6->7: register renames (free)
    { u64 t;
      t = st[ 8]; st[ 8] = st[12]; st[12] = t;
      t = st[ 9]; st[ 9] = st[13]; st[13] = t;
      t = st[10]; st[10] = st[14]; st[14] = t;
      t = st[11]; st[11] = st[15]; st[15] = t; }
    { u64 t;
      t = st[ 4]; st[ 4] = st[ 6]; st[ 6] = t;
      t = st[ 5]; st[ 5] = st[ 7]; st[ 7] = t;
      t = st[12]; st[12] = st[14]; st[14] = t;
      t = st[13]; st[13] = st[15]; st[15] = t; }
    { u64 t;
      t = st[ 2]; st[ 2] = st[ 3]; st[ 3] = t;
      t = st[ 6]; st[ 6] = st[ 7]; st[ 7] = t;
      t = st[10]; st[10] = st[11]; st[11] = t;
      t = st[14]; st[14] = st[15]; st[15] = t; }
    // q7->q8: half-swap odd-k vecs
#pragma unroll
    for (int k = 1; k < 16; k += 2) {
        float a, bb; unpack2(st[k], a, bb);
        st[k] = pack2(bb, a);
    }
    // q8->q0: p=1 halves flip logical lane bit3 -> physical mask pi(8)=12
#pragma unroll
    for (int k = 0; k < 16; ++k) {
        float a, bb; unpack2(st[k], a, bb);
        bb = __shfl_xor_sync(FULL_MASK, bb, 12);
        st[k] = pack2(a, bb);
    }

    // ========== Layer 2 (deferred space, tangent form) ==========
    {
        const int pmask[4] = {12, 6, 3, 1};
#pragma unroll
        for (int q = 0; q < 4; ++q) {
            const int lm = 8 >> q;
            const int pm = pmask[q];
            const float t = s_vt[1][c][q];
            const float sts = (lam4 & lm) ? t : -t;
            const u64 t2 = pack2(sts, sts);
#pragma unroll
            for (int k = 0; k < 16; ++k) {
                float a, bb; unpack2(st[k], a, bb);
                const float pa = __shfl_xor_sync(FULL_MASK, a, pm);
                const float pb = __shfl_xor_sync(FULL_MASK, bb, pm);
                st[k] = fma2(t2, pack2(pa, pb), st[k]);
            }
        }
    }
#pragma unroll
    for (int q = 4; q < 8; ++q) {
        const int m2 = 1 << (7 - q);
        const float t = s_vt[1][c][q];
        const u64 tp = pack2(t, t), tn = pack2(-t, -t);
#pragma unroll
        for (int k = 0; k < 16; ++k)
            if (!(k & m2)) {
                const u64 a = st[k], bb = st[k + m2];
                st[k]      = fma2(tn, bb, a);
                st[k + m2] = fma2(tp, a, bb);
            }
    }
    {
        const float t = s_vt[1][c][8];
        const u64 tpm = pack2(-t, t);
#pragma unroll
        for (int k = 0; k < 16; ++k) {
            float a, bb; unpack2(st[k], a, bb);
            st[k] = fma2(tpm, pack2(bb, a), st[k]);
        }
    }

    // --- Measurement (diagonal Pauli strings; cos product restored as S^2) ---
    u64 accE = 0ull, accO = 0ull;
#pragma unroll
    for (int k = 0; k < 16; ++k) {
        const u64 p = mul2(st[k], st[k]);
        if ((0x9669 >> k) & 1) accE = add2(accE, p);   // popc(k) even
        else                   accO = add2(accO, p);
    }
    float e0, e1, o0, o1;
    unpack2(accE, e0, e1); unpack2(accO, o0, o1);
    const float s2 = s_s2[c];
    const float sp = e0 + o1, sm = e1 + o0;
    const float tot = (sp + sm) * s2;
    const float dif = (sp - sm) * s2;

    // z0: per-half 4-level reduce
    float u = (__popc(lam4 & 7) & 1) ? -dif : dif;
    u += __shfl_xor_sync(FULL_MASK, u, 8);
    u += __shfl_xor_sync(FULL_MASK, u, 4);
    u += __shfl_xor_sync(FULL_MASK, u, 2);
    u += __shfl_xor_sync(FULL_MASK, u, 1);

    // z1/z2 factored: reduce over lam1-class subgroup {1,6,10}, cross mask 2
    float y = (__popc(lam4 & 12) & 1) ? -tot : tot;
    y += __shfl_xor_sync(FULL_MASK, y, 1);
    y += __shfl_xor_sync(FULL_MASK, y, 6);
    y += __shfl_xor_sync(FULL_MASK, y, 10);
    const float w = __shfl_xor_sync(FULL_MASK, y, 2);

    if (l4 == 0) {                       // lanes 0 (site A) and 16 (site B)
        // site index = ((b*32+shh)*32 + 2*wp + s)*3 + c ; out base = 3*that.
        const int base = 3 * (((b * 32 + shh) * 32 + 2 * wp + s) * 3 + c);
        out[base + 0] = u;
        out[base + 1] = y + w;           // lam4(0)=0 -> lam1-class 0
        out[base + 2] = y - w;
    }
}

extern "C" void kernel_launch(void* const* d_in, const int* in_sizes, int n_in,
                              void* d_out, int out_size) {
    const float* x  = (const float*)d_in[0];
    const float* qp = (const float*)d_in[1];
    float* out = (float*)d_out;
    // 12288 site-pair warps / 4 warps per 128-thread block = 3072 blocks
    quanv_main<<<3072, 128>>>(x, qp, out);
}

// round 14
// speedup vs baseline: 1.7587x; 1.1913x over previous
#include <cuda_runtime.h>

#define FULL_MASK 0xFFFFFFFFu
typedef unsigned long long u64;

// ---------- packed f32x2 helpers (sm_100a) ----------
__device__ __forceinline__ u64 pack2(float a, float b) {
    u64 d; asm("mov.b64 %0, {%1, %2};" : "=l"(d) : "f"(a), "f"(b)); return d;
}
__device__ __forceinline__ void unpack2(u64 v, float& a, float& b) {
    asm("mov.b64 {%0, %1}, %2;" : "=f"(a), "=f"(b) : "l"(v));
}
__device__ __forceinline__ u64 fma2(u64 a, u64 b, u64 c) {
    u64 d; asm("fma.rn.f32x2 %0, %1, %2, %3;" : "=l"(d) : "l"(a), "l"(b), "l"(c)); return d;
}
__device__ __forceinline__ u64 mul2(u64 a, u64 b) {
    u64 d; asm("mul.rn.f32x2 %0, %1, %2;" : "=l"(d) : "l"(a), "l"(b)); return d;
}
__device__ __forceinline__ u64 add2(u64 a, u64 b) {
    u64 d; asm("add.rn.f32x2 %0, %1, %2;" : "=l"(d) : "l"(a), "l"(b)); return d;
}

// 16-lane-per-site layout. Warp = 2 sites (lane bit4 = site s; l4 = lane&15).
// Per-thread state: 16 f32x2 regs. Amp index i = l4*32 + k*2 + p:
//   q0..q3 <-> l4 bits 3..0, q4..q7 <-> k bits 3..0, q8 <-> pair bit p.
// Layer-1 CNOT chain q0->1->2->3 is DEFERRED (logical lam4 = 4-bit prefix-xor).
// Variational RYs in TANGENT FORM (18 cos factors -> one S^2 at measurement).
// NEW: layer-1's four LANE-qubit RYs are folded into the state build via a
// transfer-matrix DP over b-bits b0..b4 (the state is still a product in the
// logical b-basis at that point), eliminating 128 shuffles per warp.
__global__ void __launch_bounds__(128, 9)
quanv_main(const float* __restrict__ x, const float* __restrict__ qp,
           float* __restrict__ out) {
    __shared__ float s_vt[2][3][9];   // tan(theta/2) for layers 1,2
    __shared__ float s_h0[3][9];      // folded layer-0 half-angles
    __shared__ float s_s2[3];         // (prod cos)^2 per channel

    const int tid = threadIdx.x;

    // ---- per-block prep ----
    if (tid < 27) {
        int cc = tid / 9, q = tid % 9;
        s_h0[cc][q] = 0.5f * qp[cc * 16 + q];
    } else if (tid < 81) {
        int u = tid - 27;
        int l = u / 27;                         // 0 -> qp layer 1, 1 -> layer 2
        int cc = (u % 27) / 9;
        int q = u % 9;
        float s, co;
        __sincosf(0.5f * qp[((l + 1) * 3 + cc) * 16 + q], &s, &co);
        s_vt[l][cc][q] = __fdividef(s, co);
    } else if (tid < 84) {
        int cc = tid - 81;
        float p = 1.0f;
#pragma unroll
        for (int l = 1; l <= 2; ++l)
#pragma unroll
            for (int q = 0; q < 9; ++q)
                p *= __cosf(0.5f * qp[(l * 3 + cc) * 16 + q]);
        s_s2[cc] = p * p;
    }
    __syncthreads();

    const int lane = tid & 31;
    const int l4   = lane & 15;
    const int s    = lane >> 4;                       // site within pair
    const int unit = (blockIdx.x * 128 + tid) >> 5;   // 0..12287
    const int c   = unit % 3;
    const int wp  = (unit / 3) & 15;
    const int shh = (unit / 48) & 31;
    const int b   = unit / 1536;
    const int sw  = 2 * wp + s;                       // this half's w

    const int c0 = (l4 >> 3) & 1, c1 = (l4 >> 2) & 1,
              c2 = (l4 >> 1) & 1, c3 = l4 & 1;

    // --- Build phase 1: qubits 0..4 + layer-1 lane-RY fold -> M(k3,p) ---
    // b-bits (layer-0 ring GF(2) map): b0=c0^p, b1=c1^c0^p, b2=c2^c1,
    // b3=c3^c2, b4=k3^c3. Lane RY on c_q pairs amps whose product values
    // differ in b_q,b_{q+1}; the 4 commuting tangent-RYs contract via DP.
    float M00, M01, M10, M11;   // M[k3][p]
    {
        float ecl[5], esl[5];
#pragma unroll
        for (int q = 0; q < 5; ++q) {
            const int di = q / 3 - 1, dj = q % 3 - 1;
            const int hi = shh + di, wj = sw + dj;
            float px = 0.0f;
            if ((unsigned)hi < 32u && (unsigned)wj < 32u)
                px = x[((b * 32 + hi) * 32 + wj) * 3 + c];
            __sincosf(fmaf(1.5707963267948966f, px, s_h0[c][q]), &esl[q], &ecl[q]);
        }
        const float t0 = s_vt[0][c][0], t1 = s_vt[0][c][1],
                    t2 = s_vt[0][c][2], t3 = s_vt[0][c][3];
        const float u0 = c0 ? t0 : -t0;
        const float u1 = c1 ? t1 : -t1;
        const float u2 = c2 ? t2 : -t2;
        const float u3 = c3 ? t3 : -t3;
        const int b2 = c2 ^ c1, b3 = c3 ^ c2;
        const float F2a = b2 ? esl[2] : ecl[2], F2b = b2 ? ecl[2] : esl[2];
        const float F3a = b3 ? esl[3] : ecl[3], F3b = b3 ? ecl[3] : esl[3];
        const float F4a = c3 ? esl[4] : ecl[4], F4b = c3 ? ecl[4] : esl[4];
#pragma unroll
        for (int p = 0; p < 2; ++p) {
            const int b0 = c0 ^ p, b1 = (c1 ^ c0) ^ p;
            const float F0a = b0 ? esl[0] : ecl[0], F0b = b0 ? ecl[0] : esl[0];
            const float F1a = b1 ? esl[1] : ecl[1], F1b = b1 ? ecl[1] : esl[1];
            const float D10 = fmaf(u0, F0b * F1b, F0a * F1a);
            const float D11 = fmaf(u0, F0b * F1a, F0a * F1b);
            const float D20 = fmaf(u1, D11 * F2b, D10 * F2a);
            const float D21 = fmaf(u1, D11 * F2a, D10 * F2b);
            const float D30 = fmaf(u2, D21 * F3b, D20 * F3a);
            const float D31 = fmaf(u2, D21 * F3a, D20 * F3b);
            const float m0 = fmaf(u3, D31 * F4b, D30 * F4a);   // k3=0
            const float m1 = fmaf(u3, D31 * F4a, D30 * F4b);   // k3=1
            if (p == 0) { M00 = m0; M10 = m1; }
            else        { M01 = m0; M11 = m1; }
        }
    }

    // --- Build phase 2: qubits 5..8 -> per-k factors, write state ---
    u64 st[16];
    {
        float ech[4], esh[4];
#pragma unroll
        for (int q = 5; q < 9; ++q) {
            const int di = q / 3 - 1, dj = q % 3 - 1;
            const int hi = shh + di, wj = sw + dj;
            float px = 0.0f;
            if ((unsigned)hi < 32u && (unsigned)wj < 32u)
                px = x[((b * 32 + hi) * 32 + wj) * 3 + c];
            __sincosf(fmaf(1.5707963267948966f, px, s_h0[c][q]), &esh[q - 5], &ech[q - 5]);
        }
        const u64 MM0 = pack2(M00, M01);         // k3=0: (p=0, p=1)
        const u64 MM1 = pack2(M10, M11);         // k3=1
        const u64 T8a = pack2(ech[3], esh[3]);   // k0=0: b8=p
        const u64 T8b = pack2(esh[3], ech[3]);   // k0=1: b8=p^1
#pragma unroll
        for (int k = 0; k < 16; ++k) {
            const int k3 = (k >> 3) & 1, k2 = (k >> 2) & 1,
                      k1 = (k >> 1) & 1, k0 = k & 1;
            const float m = ((k2 ^ k3) ? esh[0] : ech[0]) *
                            ((k1 ^ k2) ? esh[1] : ech[1]) *
                            ((k0 ^ k1) ? esh[2] : ech[2]);
            st[k] = mul2(mul2(k3 ? MM1 : MM0, pack2(m, m)), k0 ? T8b : T8a);
        }
    }

    const int lam4 = l4 ^ (l4 >> 1) ^ (l4 >> 2) ^ (l4 >> 3);

    // ========== Layer 1 (lane RYs already folded into the build) ==========
    // reg RYs q4..q7: a' = a - t*b ; b' = b + t*a
#pragma unroll
    for (int q = 4; q < 8; ++q) {
        const int m2 = 1 << (7 - q);
        const float t = s_vt[0][c][q];
        const u64 tp = pack2(t, t), tn = pack2(-t, -t);
#pragma unroll
        for (int k = 0; k < 16; ++k)
            if (!(k & m2)) {
                const u64 a = st[k], bb = st[k + m2];
                st[k]      = fma2(tn, bb, a);
                st[k + m2] = fma2(tp, a, bb);
            }
    }
    // pair RY q8: st' = st + (-t,+t)*swap(st)
    {
        const float t = s_vt[0][c][8];
        const u64 tpm = pack2(-t, t);
#pragma unroll
        for (int k = 0; k < 16; ++k) {
            float a, bb; unpack2(st[k], a, bb);
            st[k] = fma2(tpm, pack2(bb, a), st[k]);
        }
    }

    // --- Layer-1 CNOT ring ---
    // q0..q3 lane segment: DEFERRED. q3->q4: ctrl = popc(l4)&1, tgt k bit 3.
    {
        const bool hi = (__popc(l4) & 1) != 0;
#pragma unroll
        for (int k = 0; k < 8; ++k) {
            const u64 a = st[k], bb = st[k + 8];
            st[k]     = hi ? bb : a;
            st[k + 8] = hi ? a : bb;
        }
    }
    // q4->5, q5->6, q6->7: register renames (free)
    { u64 t;
      t = st[ 8]; st[ 8] = st[12]; st[12] = t;
      t = st[ 9]; st[ 9] = st[13]; st[13] = t;
      t = st[10]; st[10] = st[14]; st[14] = t;
      t = st[11]; st[11] = st[15]; st[15] = t; }
    { u64 t;
      t = st[ 4]; st[ 4] = st[ 6]; st[ 6] = t;
      t = st[ 5]; st[ 5] = st[ 7]; st[ 7] = t;
      t = st[12]; st[12] = st[14]; st[14] = t;
      t = st[13]; st[13] = st[15]; st[15] = t; }
    { u64 t;
      t = st[ 2]; st[ 2] = st[ 3]; st[ 3] = t;
      t = st[ 6]; st[ 6] = st[ 7]; st[ 7] = t;
      t = st[10]; st[10] = st[11]; st[11] = t;
      t = st[14]; st[14] = st[15]; st[15] = t; }
    // q7->q8: half-swap odd-k vecs
#pragma unroll
    for (int k = 1; k < 16; k += 2) {
        float a, bb; unpack2(st[k], a, bb);
        st[k] = pack2(bb, a);
    }
    // q8->q0: p=1 halves flip logical lane bit3 -> physical mask pi(8)=12
#pragma unroll
    for (int k = 0; k < 16; ++k) {
        float a, bb; unpack2(st[k], a, bb);
        bb = __shfl_xor_sync(FULL_MASK, bb, 12);
        st[k] = pack2(a, bb);
    }

    // ========== Layer 2 (deferred space, tangent form) ==========
    {
        const int pmask[4] = {12, 6, 3, 1};
#pragma unroll
        for (int q = 0; q < 4; ++q) {
            const int lm = 8 >> q;
            const int pm = pmask[q];
            const float t = s_vt[1][c][q];
            const float sts = (lam4 & lm) ? t : -t;
            const u64 t2 = pack2(sts, sts);
#pragma unroll
            for (int k = 0; k < 16; ++k) {
                float a, bb; unpack2(st[k], a, bb);
                const float pa = __shfl_xor_sync(FULL_MASK, a, pm);
                const float pb = __shfl_xor_sync(FULL_MASK, bb, pm);
                st[k] = fma2(t2, pack2(pa, pb), st[k]);
            }
        }
    }
#pragma unroll
    for (int q = 4; q < 8; ++q) {
        const int m2 = 1 << (7 - q);
        const float t = s_vt[1][c][q];
        const u64 tp = pack2(t, t), tn = pack2(-t, -t);
#pragma unroll
        for (int k = 0; k < 16; ++k)
            if (!(k & m2)) {
                const u64 a = st[k], bb = st[k + m2];
                st[k]      = fma2(tn, bb, a);
                st[k + m2] = fma2(tp, a, bb);
            }
    }
    {
        const float t = s_vt[1][c][8];
        const u64 tpm = pack2(-t, t);
#pragma unroll
        for (int k = 0; k < 16; ++k) {
            float a, bb; unpack2(st[k], a, bb);
            st[k] = fma2(tpm, pack2(bb, a), st[k]);
        }
    }

    // --- Measurement (diagonal Pauli strings; cos product restored as S^2) ---
    u64 accE = 0ull, accO = 0ull;
#pragma unroll
    for (int k = 0; k < 16; ++k) {
        const u64 p = mul2(st[k], st[k]);
        if ((0x9669 >> k) & 1) accE = add2(accE, p);   // popc(k) even
        else                   accO = add2(accO, p);
    }
    float e0, e1, o0, o1;
    unpack2(accE, e0, e1); unpack2(accO, o0, o1);
    const float s2 = s_s2[c];
    const float sp = e0 + o1, sm = e1 + o0;
    const float tot = (sp + sm) * s2;
    const float dif = (sp - sm) * s2;

    // z0: per-half 4-level reduce
    float u = (__popc(lam4 & 7) & 1) ? -dif : dif;
    u += __shfl_xor_sync(FULL_MASK, u, 8);
    u += __shfl_xor_sync(FULL_MASK, u, 4);
    u += __shfl_xor_sync(FULL_MASK, u, 2);
    u += __shfl_xor_sync(FULL_MASK, u, 1);

    // z1/z2 factored: reduce over lam1-class subgroup {1,6,10}, cross mask 2
    float y = (__popc(lam4 & 12) & 1) ? -tot : tot;
    y += __shfl_xor_sync(FULL_MASK, y, 1);
    y += __shfl_xor_sync(FULL_MASK, y, 6);
    y += __shfl_xor_sync(FULL_MASK, y, 10);
    const float w = __shfl_xor_sync(FULL_MASK, y, 2);

    if (l4 == 0) {                       // lanes 0 (site A) and 16 (site B)
        const int base = 3 * (((b * 32 + shh) * 32 + 2 * wp + s) * 3 + c);
        out[base + 0] = u;
        out[base + 1] = y + w;           // lam4(0)=0 -> lam1-class 0
        out[base + 2] = y - w;
    }
}

extern "C" void kernel_launch(void* const* d_in, const int* in_sizes, int n_in,
                              void* d_out, int out_size) {
    const float* x  = (const float*)d_in[0];
    const float* qp = (const float*)d_in[1];
    float* out = (float*)d_out;
    // 12288 site-pair warps / 4 warps per 128-thread block = 3072 blocks
    quanv_main<<<3072, 128>>>(x, qp, out);
}